// round 1
// baseline (speedup 1.0000x reference)
#include <cuda_runtime.h>
#include <cstdint>

#define BH  32
#define T   8192
#define DH  64
#define BSZ 128
#define NB  64      // buckets
#define HH  4       // h // 2

// ---------------- scratch (no cudaMalloc allowed) ----------------
__device__ float g_qsum  [BH*NB*DH];
__device__ float g_ksum  [BH*NB*DH];
__device__ float g_W     [BH*NB*DH];
__device__ float g_qfirst[BH*NB*DH];
__device__ float g_sq    [BH*NB*DH];
__device__ float g_sk    [BH*NB*DH];
__device__ int   g_sel   [BH*NB];
__device__ float g_wgt   [BH*NB];

__device__ __forceinline__ int rot_idx(int g, bool special) {
    // rolled by -(BSZ-1): x'[t] = x[(t + 127) mod T]
    return special ? ((g + BSZ - 1) & (T - 1)) : g;
}

// ---------------- K1: per-bucket stats on rotated q/k ----------------
// sumq (bucket sum of q), ksum (bucket sum of k), qfirst (first q row),
// W = sum_j (in-bucket inclusive prefix of k up to j) / (global_idx+1)
__global__ void k_bucket_stats(const float* __restrict__ q,
                               const float* __restrict__ k)
{
    int blk = blockIdx.x;            // bh*NB + u
    int bh  = blk >> 6, u = blk & 63;
    int d   = threadIdx.x;           // 0..63
    bool special = ((bh & 7) >= HH);
    const float* qb = q + (size_t)bh * T * DH;
    const float* kb = k + (size_t)bh * T * DH;
    int base = u * BSZ;

    float runk = 0.f, W = 0.f, sumq = 0.f, qfirst = 0.f;
    #pragma unroll 8
    for (int j = 0; j < BSZ; ++j) {
        int src = rot_idx(base + j, special);
        float qv = qb[(size_t)src * DH + d];
        float kv = kb[(size_t)src * DH + d];
        if (j == 0) qfirst = qv;
        sumq += qv;
        runk += kv;
        W += runk / (float)(base + j + 1);
    }
    int o = blk * DH + d;
    g_qsum[o] = sumq; g_ksum[o] = runk; g_W[o] = W; g_qfirst[o] = qfirst;
}

// ---------------- K2: prefix over buckets -> sq, sk ----------------
__global__ void k_prefix()
{
    __shared__ float H[NB];
    int bh = blockIdx.x;
    int d  = threadIdx.x;            // 0..63
    {   // H[u] = sum_{j=1..128} 1/(u*128 + j), one u per thread
        int u = d;
        float h = 0.f;
        for (int j = 1; j <= BSZ; ++j) h += 1.0f / (float)(u * BSZ + j);
        H[u] = h;
    }
    __syncthreads();

    float prefQ = 0.f, prefK = 0.f;
    for (int u = 0; u < NB; ++u) {
        int o = (bh * NB + u) * DH + d;
        g_sq[o] = (prefQ + g_qfirst[o]) / (float)(u * BSZ + 1);
        g_sk[o] = prefK * H[u] + g_W[o];
        prefQ += g_qsum[o];
        prefK += g_ksum[o];
    }
}

// ---------------- K3: routing: per-bucket (sel, weight) ----------------
// logits[v] over augmented columns v=0..u (v=0 is the zero "null" column),
// softmax over v in [0,u], keep argmax among v in [0,u-1].
__global__ void k_route()
{
    __shared__ float ssk[NB][DH + 1];   // padded vs bank conflicts
    int bh  = blockIdx.x;
    int tid = threadIdx.x;              // 0..63, tid = u

    for (int r = 0; r < NB; ++r)
        ssk[r][tid] = g_sk[(bh * NB + r) * DH + tid];
    __syncthreads();

    int u = tid;
    float qrow[DH];
    #pragma unroll 8
    for (int d = 0; d < DH; ++d) qrow[d] = g_sq[(bh * NB + u) * DH + d];

    float lg[NB + 1];
    lg[0] = 0.f;                        // null column: dot with 0
    for (int vv = 1; vv <= u; ++vv) {
        float s = 0.f;
        #pragma unroll 8
        for (int d = 0; d < DH; ++d) s += qrow[d] * ssk[vv - 1][d];
        lg[vv] = s * 0.125f;
    }
    if (u == 0) {
        g_sel[bh * NB] = 0;
        g_wgt[bh * NB] = 0.f;
        return;
    }
    float m = 0.f;                      // lg[0] = 0 included
    for (int vv = 1; vv <= u; ++vv) m = fmaxf(m, lg[vv]);
    float ssum = 0.f;
    for (int vv = 0; vv <= u; ++vv) ssum += expf(lg[vv] - m);
    // argmax among v in [0, u-1], first occurrence on tie
    int best = 0; float bl = lg[0];
    for (int vv = 1; vv <= u - 1; ++vv)
        if (lg[vv] > bl) { bl = lg[vv]; best = vv; }
    g_sel[bh * NB + u] = best;
    g_wgt[bh * NB + u] = expf(bl - m) / ssum;
}

// ---------------- K4: per-(bh,bucket) attention tile ----------------
__global__ void __launch_bounds__(128)
k_attn(const float* __restrict__ q, const float* __restrict__ k,
       const float* __restrict__ v, const float* __restrict__ nk,
       const float* __restrict__ nv, float* __restrict__ out)
{
    extern __shared__ float4 sm[];
    float4* K4 = sm;                 // [256][16] float4
    float4* V4 = sm + 256 * 16;

    int blk = blockIdx.x;
    int bh  = blk >> 6, u = blk & 63;
    int h   = bh & 7;
    bool special = (h >= HH);
    bool smask   = special && (u == NB - 1);

    int   selv = g_sel[bh * NB + u];
    float w    = g_wgt[bh * NB + u];

    const float* kb = k + (size_t)bh * T * DH;
    const float* vb = v + (size_t)bh * T * DH;
    int tid = threadIdx.x;

    // stage K_aug / V_aug: rows [0,128) = w * (selected bucket or null);
    // rows [128,256) = own bucket (rotated)
    for (int idx = tid; idx < 256 * 16; idx += 128) {
        int r = idx >> 4, c = idx & 15;
        float4 kk, vv;
        if (r < BSZ) {
            if (selv == 0) {
                kk = reinterpret_cast<const float4*>(nk + h * DH)[c];
                vv = reinterpret_cast<const float4*>(nv + h * DH)[c];
            } else {
                int src = rot_idx((selv - 1) * BSZ + r, special);
                kk = reinterpret_cast<const float4*>(kb + (size_t)src * DH)[c];
                vv = reinterpret_cast<const float4*>(vb + (size_t)src * DH)[c];
            }
            kk.x *= w; kk.y *= w; kk.z *= w; kk.w *= w;
            vv.x *= w; vv.y *= w; vv.z *= w; vv.w *= w;
        } else {
            int src = rot_idx(u * BSZ + (r - BSZ), special);
            kk = reinterpret_cast<const float4*>(kb + (size_t)src * DH)[c];
            vv = reinterpret_cast<const float4*>(vb + (size_t)src * DH)[c];
        }
        K4[idx] = kk; V4[idx] = vv;
    }

    int i  = tid;                    // my Q row within bucket
    int gq = u * BSZ + i;
    const float* qp = q + ((size_t)bh * T + rot_idx(gq, special)) * DH;
    float4 qr[16];
    #pragma unroll
    for (int c = 0; c < 16; ++c)
        qr[c] = reinterpret_cast<const float4*>(qp)[c];
    __syncthreads();

    float m = -1e30f, l = 0.f;
    float4 acc[16];
    #pragma unroll
    for (int c = 0; c < 16; ++c) acc[c] = make_float4(0.f, 0.f, 0.f, 0.f);

    for (int j = 0; j < 2 * BSZ; ++j) {
        bool ok = smask
            ? ((i == 0) ? (j <= BSZ) : (j > BSZ && (j - BSZ) <= i))
            : ((j < BSZ) || ((j - BSZ) <= i));
        if (!ok) continue;

        float sd = 0.f;
        const float4* kr = K4 + j * 16;
        #pragma unroll
        for (int c = 0; c < 16; ++c) {
            float4 kk = kr[c];
            sd += qr[c].x * kk.x + qr[c].y * kk.y
                + qr[c].z * kk.z + qr[c].w * kk.w;
        }
        sd *= 0.125f;

        if (sd > m) {
            float corr = __expf(m - sd);   // m==-1e30 -> corr==0
            m = sd;
            l *= corr;
            #pragma unroll
            for (int c = 0; c < 16; ++c) {
                acc[c].x *= corr; acc[c].y *= corr;
                acc[c].z *= corr; acc[c].w *= corr;
            }
        }
        float p = __expf(sd - m);
        l += p;
        const float4* vr = V4 + j * 16;
        #pragma unroll
        for (int c = 0; c < 16; ++c) {
            float4 vv = vr[c];
            acc[c].x += p * vv.x; acc[c].y += p * vv.y;
            acc[c].z += p * vv.z; acc[c].w += p * vv.w;
        }
    }

    float inv = 1.0f / l;
    // inverse roll (+127) for special heads == same index map as the input roll
    float* op = out + ((size_t)bh * T + rot_idx(gq, special)) * DH;
    #pragma unroll
    for (int c = 0; c < 16; ++c) {
        float4 a = acc[c];
        a.x *= inv; a.y *= inv; a.z *= inv; a.w *= inv;
        reinterpret_cast<float4*>(op)[c] = a;
    }
}

// ---------------- launch ----------------
extern "C" void kernel_launch(void* const* d_in, const int* in_sizes, int n_in,
                              void* d_out, int out_size)
{
    (void)in_sizes; (void)n_in; (void)out_size;
    const float* q  = (const float*)d_in[0];
    const float* k  = (const float*)d_in[1];
    const float* v  = (const float*)d_in[2];
    const float* nk = (const float*)d_in[3];
    const float* nv = (const float*)d_in[4];
    float* out = (float*)d_out;

    const int smem = 2 * 256 * 16 * (int)sizeof(float4);   // 128 KB
    cudaFuncSetAttribute(k_attn, cudaFuncAttributeMaxDynamicSharedMemorySize, smem);

    k_bucket_stats<<<BH * NB, DH>>>(q, k);
    k_prefix<<<BH, DH>>>();
    k_route<<<BH, DH>>>();
    k_attn<<<BH * NB, 128, smem>>>(q, k, v, nk, nv, out);
}